// round 17
// baseline (speedup 1.0000x reference)
#include <cuda_runtime.h>
#include <cuda_fp16.h>
#include <cstdint>
#include <cstddef>

// ScaledDotProductAttention B=16, S=2048, D=128 fp32 (sm_100 classic mma.sync).
// Out = context [16,2048,128] ++ attention [16,2048,2048].
//
// Round 17 = round-12 task bodies + persistent dynamic scheduler.
// Grid 256 equal CTAs over 148 SMs wastes 27% of wave 2 (makespan 2T vs
// ideal 1.73T). Instead: 148 persistent CTAs pull 512 tasks from a global
// atomic counter (0-255: pass-1 of block, 256-511: pass-2 of block-256).
// All p1 ids are handed out (=> executing) before any p2 id, so p2's spin
// on the per-block done flag is bounded by one in-flight p1.
//
//  cvt_kv : K -> fp16; V -> fp16 transposed pair-words; resets task counter
//           and done flags (stream-ordered before attn1; replay-safe).
//  p1 task: K-only QK (128-key groups, 3-slot ring), p=exp2(S) -> g_ph fp16
//           (st.global.cg); row sums -> g_rinv; fence + st.release done.
//  p2 task: cp.async P+V tiles; LDSM P as PV A-frags; attention =
//           unpack(P)*rinv; O += P V; context = O*rinv.

#define BATCH 16
#define SEQ   2048
#define DIM   128

#define KSTR  68
#define VSTR2 36
#define PSTR  36
#define KBUF (64*KSTR)            // 4352
#define VBUF (128*VSTR2)          // 4608
#define PBUF (128*PSTR)           // 4608
#define STAGE_W (PBUF + VBUF)     // 9216
#define NBUF 4
#define SMEM_WORDS (NBUF * STAGE_W)   // 36864 words = 147,456 B
#define NBLK 256
#define NSM  148

__device__ __half   g_kh[BATCH * SEQ * DIM];
__device__ uint32_t g_vh[BATCH * DIM * (SEQ / 2)];
__device__ uint32_t g_ph[(size_t)BATCH * SEQ * SEQ / 2];
__device__ float    g_rinv[BATCH * SEQ];
__device__ uint32_t g_task;
__device__ uint32_t g_done[NBLK];

__device__ __forceinline__ uint32_t smem_u32(const void* p) {
    uint32_t a;
    asm("{ .reg .u64 t; cvta.to.shared.u64 t, %1; cvt.u32.u64 %0, t; }" : "=r"(a) : "l"(p));
    return a;
}
__device__ __forceinline__ float ex2(float x) {
    float y; asm("ex2.approx.f32 %0, %1;" : "=f"(y) : "f"(x)); return y;
}
__device__ __forceinline__ uint32_t h2(float a, float b) {
    uint32_t r;
    asm("cvt.rn.f16x2.f32 %0, %2, %1;" : "=r"(r) : "f"(a), "f"(b));
    return r;
}
__device__ __forceinline__ float2 h22f2(uint32_t u) {
    __half2 h = *(__half2*)&u;
    return __half22float2(h);
}
__device__ __forceinline__ void stcg(uint32_t* p, uint32_t v) {
    asm volatile("st.global.cg.u32 [%0], %1;" :: "l"(p), "r"(v));
}
__device__ __forceinline__ uint32_t ld_acq(const uint32_t* p) {
    uint32_t v;
    asm volatile("ld.acquire.gpu.u32 %0, [%1];" : "=r"(v) : "l"(p) : "memory");
    return v;
}
__device__ __forceinline__ void st_rel(uint32_t* p, uint32_t v) {
    asm volatile("st.release.gpu.u32 [%0], %1;" :: "l"(p), "r"(v) : "memory");
}
__device__ __forceinline__ void mma_f16(float& c0, float& c1, float& c2, float& c3,
                                        uint32_t a0, uint32_t a1, uint32_t a2, uint32_t a3,
                                        uint32_t b0, uint32_t b1) {
    asm("mma.sync.aligned.m16n8k16.row.col.f32.f16.f16.f32 "
        "{%0,%1,%2,%3}, {%4,%5,%6,%7}, {%8,%9}, {%0,%1,%2,%3};"
        : "+f"(c0), "+f"(c1), "+f"(c2), "+f"(c3)
        : "r"(a0), "r"(a1), "r"(a2), "r"(a3), "r"(b0), "r"(b1));
}
__device__ __forceinline__ void ldsm4(uint32_t& r0, uint32_t& r1, uint32_t& r2,
                                      uint32_t& r3, uint32_t addr) {
    asm volatile("ldmatrix.sync.aligned.m8n8.x4.shared.b16 {%0,%1,%2,%3}, [%4];"
                 : "=r"(r0), "=r"(r1), "=r"(r2), "=r"(r3) : "r"(addr));
}

#define CP16(dst, src) \
    asm volatile("cp.async.cg.shared.global [%0], [%1], 16;" :: "r"(dst), "l"(src))
#define CP_COMMIT() asm volatile("cp.async.commit_group;" ::: "memory")
#define CP_WAIT(n)  asm volatile("cp.async.wait_group %0;" :: "n"(n) : "memory")

__device__ __forceinline__ void issue_k_grp128(uint32_t smb, const __half* kh,
                                               int grp, int tid) {
    const uint32_t base = smb + (uint32_t)((grp % 3) * 2 * KBUF) * 4;
    const char* kp = (const char*)(kh + (size_t)grp * 128 * DIM);
#pragma unroll
    for (int j = 0; j < 8; j++) {
        int i = tid + j * 256;
        int kr = i >> 4, kc = i & 15;
        uint32_t off = (uint32_t)(((kr >> 6) * KBUF + (kr & 63) * KSTR) * 4 + kc * 16);
        CP16(base + off, kp + kr * 256 + kc * 16);
    }
    CP_COMMIT();
}

__device__ __forceinline__ void issue_stage2(uint32_t smb, const char* php,
                                             const uint32_t* vh, int s, int tid) {
    const uint32_t base = smb + (uint32_t)((s & (NBUF - 1)) * STAGE_W) * 4;
    const char* pp = php + (size_t)s * 128;
    const char* vp = (const char*)(vh + (size_t)s * 32);
#pragma unroll
    for (int j = 0; j < 4; j++) {
        int i = tid + j * 256;
        int r = i >> 3, c = i & 7;
        CP16(base + (uint32_t)(r * PSTR * 4 + c * 16), pp + (size_t)r * 4096 + c * 16);
        CP16(base + (uint32_t)(PBUF * 4 + r * VSTR2 * 4 + c * 16),
             vp + (size_t)r * (SEQ / 2) * 4 + c * 16);
    }
    CP_COMMIT();
}

// K -> fp16; V -> fp16 transposed pair-words; reset scheduler state.
__global__ void __launch_bounds__(256)
cvt_kv(const float* __restrict__ k, const float* __restrict__ v) {
    const int tid = threadIdx.x;
    if (blockIdx.x == 0) {
        g_done[tid] = 0;
        if (tid == 0) g_task = 0;
    }
    const size_t nkw = (size_t)BATCH * SEQ * DIM / 2;
    for (size_t w = (size_t)blockIdx.x * 256 + tid; w < nkw; w += (size_t)gridDim.x * 256) {
        float2 kf = ((const float2*)k)[w];
        ((uint32_t*)g_kh)[w] = h2(kf.x, kf.y);
    }
    __shared__ float s[64][33];
    const int bx = blockIdx.x;
    const int b  = bx >> 7;
    const int pt = (bx >> 2) & 31;
    const int dt = bx & 3;
    const float* vb = v + ((size_t)b * SEQ + pt * 64) * DIM + dt * 32;
#pragma unroll
    for (int j = 0; j < 8; j++) {
        int i = tid + j * 256;
        int kk = i >> 5, dd = i & 31;
        s[kk][dd] = vb[(size_t)kk * DIM + dd];
    }
    __syncthreads();
    uint32_t* dst = g_vh + (size_t)b * DIM * (SEQ / 2) + (size_t)(dt * 32) * (SEQ / 2) + pt * 32;
#pragma unroll
    for (int j = 0; j < 4; j++) {
        int i = tid + j * 256;
        int pp = i & 31, dd = i >> 5;
        dst[(size_t)dd * (SEQ / 2) + pp] = h2(s[2 * pp][dd], s[2 * pp + 1][dd]);
    }
}

__global__ void __launch_bounds__(256, 1)
attn1(const float* __restrict__ qg_, float* __restrict__ out) {
    extern __shared__ float sm[];
    __shared__ uint32_t s_task;
    const uint32_t smb = smem_u32(sm);

    const int tid = threadIdx.x;
    const int warp = tid >> 5, lane = tid & 31;
    const int g = lane >> 2, qq = lane & 3;
    const int row0 = warp * 16 + g;

    const uint32_t kln = (uint32_t)((lane & 7) * KSTR * 4 + 16 * (lane >> 3));
    const uint32_t vln = (uint32_t)((lane & 7) * VSTR2 * 4 + ((lane >> 3) & 1) * 16
                                    + (lane >> 4) * 8 * VSTR2 * 4);
    const uint32_t pln = (uint32_t)((16 * warp + (lane & 15)) * PSTR * 4
                                    + (lane >> 4) * 16);
    const float qsc = 0.088388347648318447f * 1.4426950408889634f;

    for (;;) {
        if (tid == 0) s_task = atomicAdd(&g_task, 1u);
        __syncthreads();
        const uint32_t task = s_task;
        __syncthreads();
        if (task >= 2 * NBLK) return;

        const int blk = (int)(task & (NBLK - 1));
        const int b = blk >> 4, qb = blk & 15;
        const size_t R0 = (size_t)b * SEQ + (size_t)qb * 128;

        if (task < NBLK) {
            // ================= PASS-1 TASK =================
            const __half* kh = g_kh + (size_t)b * SEQ * DIM;
            issue_k_grp128(smb, kh, 0, tid);
            issue_k_grp128(smb, kh, 1, tid);

            const float* q0 = qg_ + (R0 + row0) * DIM;
            const float* q1 = q0 + 8 * DIM;
            uint32_t qa[8][4];
#pragma unroll
            for (int t = 0; t < 8; t++) {
                int c0 = 16 * t + 2 * qq;
                qa[t][0] = h2(q0[c0] * qsc,     q0[c0 + 1] * qsc);
                qa[t][1] = h2(q1[c0] * qsc,     q1[c0 + 1] * qsc);
                qa[t][2] = h2(q0[c0 + 8] * qsc, q0[c0 + 9] * qsc);
                qa[t][3] = h2(q1[c0 + 8] * qsc, q1[c0 + 9] * qsc);
            }

            uint32_t* pr0b = g_ph + (R0 + row0) * (SEQ / 2) + qq;
            float l0 = 0.f, l1 = 0.f;
            for (int t = 0; t < 16; ++t) {
                if (t < 15) { CP_WAIT(1); } else { CP_WAIT(0); }
                __syncthreads();
                if (t + 2 < 16) issue_k_grp128(smb, kh, t + 2, tid);

                const uint32_t slotb = smb + (uint32_t)((t % 3) * 2 * KBUF) * 4;
#pragma unroll
                for (int h = 0; h < 2; h++) {
                    const uint32_t kbase = slotb + (uint32_t)(h * KBUF * 4) + kln;
                    float cf[8][4];
#pragma unroll
                    for (int i = 0; i < 8; i++)
                        { cf[i][0] = cf[i][1] = cf[i][2] = cf[i][3] = 0.f; }
#pragma unroll
                    for (int u = 0; u < 4; u++) {
#pragma unroll
                        for (int nt = 0; nt < 8; nt++) {
                            uint32_t b00, b01, b10, b11;
                            ldsm4(b00, b01, b10, b11,
                                  kbase + (uint32_t)(nt * 8 * KSTR * 4 + u * 64));
                            mma_f16(cf[nt][0], cf[nt][1], cf[nt][2], cf[nt][3],
                                    qa[2*u][0], qa[2*u][1], qa[2*u][2], qa[2*u][3],
                                    b00, b01);
                            mma_f16(cf[nt][0], cf[nt][1], cf[nt][2], cf[nt][3],
                                    qa[2*u+1][0], qa[2*u+1][1], qa[2*u+1][2], qa[2*u+1][3],
                                    b10, b11);
                        }
                    }
                    uint32_t* pr0 = pr0b + t * 64 + h * 32;
                    uint32_t* pr1 = pr0 + 8 * (SEQ / 2);
#pragma unroll
                    for (int nt = 0; nt < 8; nt++) {
                        float p0 = ex2(cf[nt][0]);
                        float p1 = ex2(cf[nt][1]);
                        float p2 = ex2(cf[nt][2]);
                        float p3 = ex2(cf[nt][3]);
                        l0 += p0 + p1; l1 += p2 + p3;
                        stcg(pr0 + 4 * nt, h2(p0, p1));
                        stcg(pr1 + 4 * nt, h2(p2, p3));
                    }
                }
            }

            l0 += __shfl_xor_sync(0xffffffffu, l0, 1);
            l0 += __shfl_xor_sync(0xffffffffu, l0, 2);
            l1 += __shfl_xor_sync(0xffffffffu, l1, 1);
            l1 += __shfl_xor_sync(0xffffffffu, l1, 2);
            if (qq == 0) {
                g_rinv[R0 + row0]     = 1.0f / l0;
                g_rinv[R0 + row0 + 8] = 1.0f / l1;
            }
            __threadfence();
            __syncthreads();
            if (tid == 0) st_rel(&g_done[blk], 1u);
        } else {
            // ================= PASS-2 TASK =================
            if (tid == 0) {
                while (ld_acq(&g_done[blk]) == 0u) __nanosleep(64);
            }
            __syncthreads();
            __threadfence();

            const uint32_t* vh = g_vh + (size_t)b * DIM * (SEQ / 2);
            float* ctx = out + R0 * DIM;
            float* att = out + (size_t)BATCH * SEQ * DIM + R0 * SEQ;
            const float r0 = g_rinv[R0 + row0];
            const float r1 = g_rinv[R0 + row0 + 8];

            const char* php = (const char*)(g_ph + R0 * (SEQ / 2));
            issue_stage2(smb, php, vh, 0, tid);
            issue_stage2(smb, php, vh, 1, tid);
            issue_stage2(smb, php, vh, 2, tid);

            float o[16][4];
#pragma unroll
            for (int i = 0; i < 16; i++) { o[i][0] = o[i][1] = o[i][2] = o[i][3] = 0.f; }

            for (int s = 0; s < 32; ++s) {
                if (s <= 28) { CP_WAIT(2); } else { CP_WAIT(0); }
                __syncthreads();
                if (s <= 28) issue_stage2(smb, php, vh, s + 3, tid);

                const uint32_t pbase = smb + (uint32_t)((s & (NBUF - 1)) * STAGE_W) * 4 + pln;
                const uint32_t vbase = smb + (uint32_t)((s & (NBUF - 1)) * STAGE_W + PBUF) * 4 + vln;

                uint32_t A[4][4];
#pragma unroll
                for (int tt = 0; tt < 4; tt++)
                    ldsm4(A[tt][0], A[tt][1], A[tt][2], A[tt][3],
                          pbase + (uint32_t)(tt * 32));

                float* a0p = att + (size_t)row0 * SEQ + 64 * s + 2 * qq;
                float* a1p = a0p + (size_t)8 * SEQ;
#pragma unroll
                for (int tt = 0; tt < 4; tt++) {
                    float2 x0 = h22f2(A[tt][0]);
                    float2 x1 = h22f2(A[tt][1]);
                    float2 x2 = h22f2(A[tt][2]);
                    float2 x3 = h22f2(A[tt][3]);
                    *(float2*)(a0p + 16 * tt)     = make_float2(x0.x * r0, x0.y * r0);
                    *(float2*)(a0p + 16 * tt + 8) = make_float2(x2.x * r0, x2.y * r0);
                    *(float2*)(a1p + 16 * tt)     = make_float2(x1.x * r1, x1.y * r1);
                    *(float2*)(a1p + 16 * tt + 8) = make_float2(x3.x * r1, x3.y * r1);
                }

#pragma unroll
                for (int tt = 0; tt < 4; tt++) {
#pragma unroll
                    for (int ndp = 0; ndp < 8; ndp++) {
                        uint32_t v00, v01, v10, v11;
                        ldsm4(v00, v01, v10, v11,
                              vbase + (uint32_t)(tt * 32 + ndp * 16 * VSTR2 * 4));
                        mma_f16(o[2*ndp][0], o[2*ndp][1], o[2*ndp][2], o[2*ndp][3],
                                A[tt][0], A[tt][1], A[tt][2], A[tt][3], v00, v01);
                        mma_f16(o[2*ndp+1][0], o[2*ndp+1][1], o[2*ndp+1][2], o[2*ndp+1][3],
                                A[tt][0], A[tt][1], A[tt][2], A[tt][3], v10, v11);
                    }
                }
            }

            float* c0p = ctx + (size_t)row0 * DIM + 2 * qq;
            float* c1p = c0p + (size_t)8 * DIM;
#pragma unroll
            for (int nd = 0; nd < 16; nd++) {
                *(float2*)(c0p + 8 * nd) = make_float2(o[nd][0] * r0, o[nd][1] * r0);
                *(float2*)(c1p + 8 * nd) = make_float2(o[nd][2] * r1, o[nd][3] * r1);
            }
        }
    }
}

extern "C" void kernel_launch(void* const* d_in, const int* in_sizes, int n_in,
                              void* d_out, int out_size) {
    const float* q = (const float*)d_in[0];
    const float* k = (const float*)d_in[1];
    const float* v = (const float*)d_in[2];
    float* out = (float*)d_out;

    cudaFuncSetAttribute(attn1, cudaFuncAttributeMaxDynamicSharedMemorySize,
                         SMEM_WORDS * 4);

    cvt_kv<<<2048, 256>>>(k, v);
    attn1<<<NSM, 256, SMEM_WORDS * 4>>>(q, out);
}